// round 13
// baseline (speedup 1.0000x reference)
#include <cuda_runtime.h>
#include <cuda_fp16.h>
#include <math.h>

// ---------------- problem constants (fixed-shape problem) ----------------
#define NN 100000
#define EE 3200000
#define F_IN 128
#define HID 64
#define NLAYER 64
#define NCLASS 47
#define ALPHA 0.1f
#define THETA 0.5f
#define SF 32.0f          // fp8 storage scale (keeps values in e4m3 normal range)
#define SFI (1.0f / 32.0f)

// ---------------- scratch (static device globals; no allocation) ---------
// Feature buffers hold PRE-SCALED rows: q = SF * dinv[r] * h[r], e4m3 fp8.
// Row NN is a phantom all-zero row used to pad edge-chunk tails.
__device__ __align__(16) float         g_x0[NN * HID];           // fp32 residual
__device__ __align__(16) unsigned char g_h8A[(NN + 1) * HID];    // ping (fp8)
__device__ __align__(16) unsigned char g_h8B[(NN + 1) * HID];    // pong (fp8)
__device__ int   g_col[EE];          // CSR column indices
__device__ int   g_rowptr[NN + 1];
__device__ int   g_cnt[NN];          // zero at load; self-cleaned each run
__device__ int   g_cursor[NN];
__device__ float g_dinv[NN];         // 1/sqrt(deg+1)
__device__ float g_rdinv[NN];        // sqrt(deg+1)
__device__ int   g_bsum[128];
__device__ int   g_is64;

__device__ __forceinline__ const unsigned char* pick8(int s) {
    return (s == 1) ? g_h8A : g_h8B;
}
__device__ __forceinline__ unsigned char* pick8_mut(int s) {
    return (s == 1) ? g_h8A : g_h8B;
}

// packed f32x2 fma: d = a*b + d
__device__ __forceinline__ void fma2(unsigned long long& d,
                                     unsigned long long a,
                                     unsigned long long b) {
    asm("fma.rn.f32x2 %0, %1, %2, %0;" : "+l"(d) : "l"(a), "l"(b));
}

// decode 4 packed e4m3 -> two half2 (features in byte order)
__device__ __forceinline__ void dec4h(unsigned int u, __half2& h0, __half2& h1) {
    unsigned int a, b;
    asm("{\n\t"
        ".reg .b16 lo, hi;\n\t"
        "mov.b32 {lo, hi}, %2;\n\t"
        "cvt.rn.f16x2.e4m3x2 %0, lo;\n\t"
        "cvt.rn.f16x2.e4m3x2 %1, hi;\n\t"
        "}" : "=r"(a), "=r"(b) : "r"(u));
    h0 = *(__half2*)&a;
    h1 = *(__half2*)&b;
}

// decode 4 packed e4m3 -> two float2
__device__ __forceinline__ void dec4(unsigned int u, float2& f0, float2& f1) {
    __half2 h0, h1;
    dec4h(u, h0, h1);
    f0 = __half22float2(h0);
    f1 = __half22float2(h1);
}

// encode two floats -> 2 packed e4m3 (hi -> upper byte)
__device__ __forceinline__ unsigned short enc2(float hi, float lo) {
    unsigned short p;
    asm("cvt.rn.satfinite.e4m3x2.f32 %0, %1, %2;" : "=h"(p) : "f"(hi), "f"(lo));
    return p;
}

// consume 2 edges (uint2 each = 8 fp8 features): depth-1 fp16 pair tree,
// then fp32 accumulate. e4m3 values are exact in fp16; one fp16 rounding
// per feature-pair (negligible vs fp8 quantization noise).
__device__ __forceinline__ void consume2(uint2 ea, uint2 eb,
                                         float& a0, float& a1, float& a2, float& a3,
                                         float& a4, float& a5, float& a6, float& a7) {
    __half2 x0, x1, x2, x3, y0, y1, y2, y3;
    dec4h(ea.x, x0, x1); dec4h(ea.y, x2, x3);
    dec4h(eb.x, y0, y1); dec4h(eb.y, y2, y3);
    __half2 s0 = __hadd2(x0, y0);
    __half2 s1 = __hadd2(x1, y1);
    __half2 s2 = __hadd2(x2, y2);
    __half2 s3 = __hadd2(x3, y3);
    float2 f0 = __half22float2(s0);
    float2 f1 = __half22float2(s1);
    float2 f2 = __half22float2(s2);
    float2 f3 = __half22float2(s3);
    a0 += f0.x; a1 += f0.y; a2 += f1.x; a3 += f1.y;
    a4 += f2.x; a5 += f2.y; a6 += f3.x; a7 += f3.y;
}

__device__ __forceinline__ int edge_at(const void* eiv, size_t idx, int is64) {
    if (is64) return (int)((const long long*)eiv)[idx];
    return ((const int*)eiv)[idx];
}

// ---------------- x0 = relu(x @ W1 + b1)  (+ inline edge-dtype detect) ----
__global__ void __launch_bounds__(256) x0_kernel(const float* __restrict__ x,
                                                 const float* __restrict__ W1,
                                                 const float* __restrict__ b1,
                                                 const unsigned int* __restrict__ eip) {
    if (blockIdx.x == 0 && threadIdx.x == 0) {
        int all0 = 1;
        for (int i = 0; i < 64; i++) {
            if (eip[2 * i + 1] != 0u) { all0 = 0; break; }
        }
        g_is64 = all0;
    }

    __shared__ __align__(16) float Ws[F_IN * HID];  // 32KB
    int tid = threadIdx.x;
    const float4* W4 = (const float4*)W1;
    float4* Ws4 = (float4*)Ws;
#pragma unroll
    for (int i = tid; i < (F_IN * HID) / 4; i += 256) Ws4[i] = W4[i];
    __syncthreads();

    int base = blockIdx.x * 64;
    int w = tid >> 5, lane = tid & 31;
    float bx = b1[2 * lane], by = b1[2 * lane + 1];
#pragma unroll 1
    for (int i = 0; i < 8; i++) {
        int r = base + w * 8 + i;
        if (r >= NN) continue;
        float ax = bx, ay = by;
        const float4* xr = (const float4*)(x + (size_t)r * F_IN);
#pragma unroll 8
        for (int kk = 0; kk < F_IN / 4; kk++) {
            float4 xv = xr[kk];
            int k = kk * 4;
            float2 w0 = ((const float2*)(Ws + (k + 0) * HID))[lane];
            float2 w1 = ((const float2*)(Ws + (k + 1) * HID))[lane];
            float2 w2 = ((const float2*)(Ws + (k + 2) * HID))[lane];
            float2 w3 = ((const float2*)(Ws + (k + 3) * HID))[lane];
            ax += xv.x * w0.x; ay += xv.x * w0.y;
            ax += xv.y * w1.x; ay += xv.y * w1.y;
            ax += xv.z * w2.x; ay += xv.z * w2.y;
            ax += xv.w * w3.x; ay += xv.w * w3.y;
        }
        float vx = fmaxf(ax, 0.f), vy = fmaxf(ay, 0.f);
        ((float2*)(g_x0 + (size_t)r * HID))[lane] = make_float2(vx, vy);
    }
}

// ---------------- CSR: count ----------------
__global__ void count_kernel(const void* __restrict__ eiv) {
    int i = blockIdx.x * blockDim.x + threadIdx.x;
    int is64 = g_is64;
    if (i < EE) {
        int dst = edge_at(eiv, (size_t)EE + i, is64);
        atomicAdd(&g_cnt[dst], 1);
    }
}

// ---------------- CSR: block-local exclusive scan (1024 per block) -------
__global__ void scan1_kernel() {
    __shared__ int sh[256];
    int t = threadIdx.x, b = blockIdx.x;
    int base = b * 1024 + t * 4;
    int v0 = (base + 0 < NN) ? g_cnt[base + 0] : 0;
    int v1 = (base + 1 < NN) ? g_cnt[base + 1] : 0;
    int v2 = (base + 2 < NN) ? g_cnt[base + 2] : 0;
    int v3 = (base + 3 < NN) ? g_cnt[base + 3] : 0;
    int s0 = v0, s1 = s0 + v1, s2 = s1 + v2, s3 = s2 + v3;
    sh[t] = s3;
    __syncthreads();
    for (int off = 1; off < 256; off <<= 1) {
        int v = (t >= off) ? sh[t - off] : 0;
        __syncthreads();
        sh[t] += v;
        __syncthreads();
    }
    int excl = sh[t] - s3;
    if (base + 0 < NN) g_rowptr[base + 0] = excl;
    if (base + 1 < NN) g_rowptr[base + 1] = excl + s0;
    if (base + 2 < NN) g_rowptr[base + 2] = excl + s1;
    if (base + 3 < NN) g_rowptr[base + 3] = excl + s2;
    if (t == 255) g_bsum[b] = sh[255];
}

// ---------------- CSR: finalize (inline bsum prefix) + dinv + seed h8A ---
__global__ void __launch_bounds__(256) scan3_kernel() {
    __shared__ int pre_sh;
    int t = threadIdx.x, b = blockIdx.x;
    if (t == 0) {
        int nb = b >> 2;
        int run = 0;
        for (int j = 0; j < nb; j++) run += g_bsum[j];
        pre_sh = run;
    }
    __syncthreads();
    int i = b * 256 + t;
    if (i < NN) {
        int rp = g_rowptr[i] + pre_sh;
        g_rowptr[i] = rp;
        g_cursor[i] = rp;
        int deg = g_cnt[i] + 1;
        float di = rsqrtf((float)deg);
        g_dinv[i] = di;
        g_rdinv[i] = sqrtf((float)deg);
        g_cnt[i] = 0;
        // seed h8A with q0 = SF * dinv * x0 (fp8 e4m3)
        float s = SF * di;
        const float4* xr = (const float4*)(g_x0 + (size_t)i * HID);
        unsigned int* hw = (unsigned int*)(g_h8A + (size_t)i * HID);
#pragma unroll
        for (int k = 0; k < 16; k++) {
            float4 v = xr[k];
            unsigned short lo = enc2(s * v.y, s * v.x);
            unsigned short hi = enc2(s * v.w, s * v.z);
            hw[k] = ((unsigned int)hi << 16) | lo;
        }
    }
    if (i == 0) g_rowptr[NN] = EE;
    if (b == 0 && t < 16) {       // phantom row NN = 0 in both buffers
        ((unsigned int*)(g_h8A + (size_t)NN * HID))[t] = 0u;
        ((unsigned int*)(g_h8B + (size_t)NN * HID))[t] = 0u;
    }
}

// ---------------- CSR: scatter ----------------
__global__ void scatter_kernel(const void* __restrict__ eiv) {
    int i = blockIdx.x * blockDim.x + threadIdx.x;
    int is64 = g_is64;
    if (i < EE) {
        int src = edge_at(eiv, (size_t)i, is64);
        int dst = edge_at(eiv, (size_t)EE + i, is64);
        int pos = atomicAdd(&g_cursor[dst], 1);
        g_col[pos] = src;
    }
}

// ---------------- fused layer --------------------------------------------
// phase 1: p[r] = (dinv[r]/SF) * (sum_edges q[c] + q[r])   (pure sum, fp8 rows)
//          s    = (1-a)*p + a*x0
// phase 2: h = relu((1-b)s + b*(s@W));  store q = SF*dinv[r]*h as fp8
__global__ void __launch_bounds__(256) layer_kernel(const float* __restrict__ Wl,
                                                    float beta, int sel_in, int sel_out) {
    __shared__ __align__(16) float Ws[HID * HID];    // 16KB
    __shared__ __align__(16) float ss[64 * 65];      // 16.6KB, pitch 65
    const unsigned char* __restrict__ hin = pick8(sel_in);
    unsigned char* __restrict__ hout = pick8_mut(sel_out);

    int tid = threadIdx.x;
    {   // stage Wl
        const float4* W4 = (const float4*)Wl;
        float4* Ws4 = (float4*)Ws;
#pragma unroll
        for (int i = tid; i < (HID * HID) / 4; i += 256) Ws4[i] = W4[i];
    }

    int base = blockIdx.x * 64;
    int w = tid >> 5, lane = tid & 31;
    int g = lane >> 3;          // edge group within a 4-edge round (0..3)
    int t = lane & 7;           // uint2 slot: features 8t..8t+7
    const unsigned FULL = 0xffffffffu;

    // -------- phase 1: warp-per-row unweighted gather, 4 edges/LDG.64 ----
    // 32 cols coalesced per chunk; 8-edge subchunks = 2 LDG rounds of 4
    // edges each, double-buffered (R9/R12 skeleton). Per-edge 64B row is
    // covered by 8 lanes x uint2. Tail lanes -> phantom row NN (zeros).
#pragma unroll 1
    for (int i = 0; i < 8; i++) {
        int rl = w * 8 + i;
        int r = base + rl;
        if (r < NN) {
            float a0 = 0.f, a1 = 0.f, a2 = 0.f, a3 = 0.f;
            float a4 = 0.f, a5 = 0.f, a6 = 0.f, a7 = 0.f;
            int e = g_rowptr[r];
            const int e1 = g_rowptr[r + 1];
#pragma unroll 1
            while (e < e1) {
                int rem = e1 - e;
                int cw = (lane < rem) ? g_col[e + lane] : NN;
                int np = rem < 32 ? rem : 32;
                int nsub = (np + 7) >> 3;

                uint2 ha0, ha1;
                {
                    int i0 = g;
                    int c0 = __shfl_sync(FULL, cw, i0); if (i0 >= np) c0 = NN;
                    int i1 = 4 + g;
                    int c1 = __shfl_sync(FULL, cw, i1); if (i1 >= np) c1 = NN;
                    ha0 = ((const uint2*)(hin + (size_t)c0 * HID))[t];
                    ha1 = ((const uint2*)(hin + (size_t)c1 * HID))[t];
                }
#pragma unroll 1
                for (int s = 1; s < nsub; s++) {
                    uint2 hb0, hb1;
                    int i0 = 8 * s + g;
                    int c0 = __shfl_sync(FULL, cw, i0); if (i0 >= np) c0 = NN;
                    int i1 = 8 * s + 4 + g;
                    int c1 = __shfl_sync(FULL, cw, i1); if (i1 >= np) c1 = NN;
                    hb0 = ((const uint2*)(hin + (size_t)c0 * HID))[t];
                    hb1 = ((const uint2*)(hin + (size_t)c1 * HID))[t];
                    consume2(ha0, ha1, a0, a1, a2, a3, a4, a5, a6, a7);
                    ha0 = hb0; ha1 = hb1;
                }
                consume2(ha0, ha1, a0, a1, a2, a3, a4, a5, a6, a7);
                e += 32;
            }
            // reduce across the 4 groups (lane-octets)
            a0 += __shfl_xor_sync(FULL, a0, 8);  a0 += __shfl_xor_sync(FULL, a0, 16);
            a1 += __shfl_xor_sync(FULL, a1, 8);  a1 += __shfl_xor_sync(FULL, a1, 16);
            a2 += __shfl_xor_sync(FULL, a2, 8);  a2 += __shfl_xor_sync(FULL, a2, 16);
            a3 += __shfl_xor_sync(FULL, a3, 8);  a3 += __shfl_xor_sync(FULL, a3, 16);
            a4 += __shfl_xor_sync(FULL, a4, 8);  a4 += __shfl_xor_sync(FULL, a4, 16);
            a5 += __shfl_xor_sync(FULL, a5, 8);  a5 += __shfl_xor_sync(FULL, a5, 16);
            a6 += __shfl_xor_sync(FULL, a6, 8);  a6 += __shfl_xor_sync(FULL, a6, 16);
            a7 += __shfl_xor_sync(FULL, a7, 8);  a7 += __shfl_xor_sync(FULL, a7, 16);
            // self loop: + q[r]
            {
                uint2 hs = ((const uint2*)(hin + (size_t)r * HID))[t];
                float2 f0, f1, f2, f3;
                dec4(hs.x, f0, f1);
                dec4(hs.y, f2, f3);
                a0 += f0.x; a1 += f0.y; a2 += f1.x; a3 += f1.y;
                a4 += f2.x; a5 += f2.y; a6 += f3.x; a7 += f3.y;
            }
            if (lane < 8) {
                float drs = g_dinv[r] * SFI;
                float4 xa = ((const float4*)(g_x0 + (size_t)r * HID))[2 * t + 0];
                float4 xb = ((const float4*)(g_x0 + (size_t)r * HID))[2 * t + 1];
                int bsh = rl * 65 + 8 * t;
                ss[bsh + 0] = (1.f - ALPHA) * (drs * a0) + ALPHA * xa.x;
                ss[bsh + 1] = (1.f - ALPHA) * (drs * a1) + ALPHA * xa.y;
                ss[bsh + 2] = (1.f - ALPHA) * (drs * a2) + ALPHA * xa.z;
                ss[bsh + 3] = (1.f - ALPHA) * (drs * a3) + ALPHA * xa.w;
                ss[bsh + 4] = (1.f - ALPHA) * (drs * a4) + ALPHA * xb.x;
                ss[bsh + 5] = (1.f - ALPHA) * (drs * a5) + ALPHA * xb.y;
                ss[bsh + 6] = (1.f - ALPHA) * (drs * a6) + ALPHA * xb.z;
                ss[bsh + 7] = (1.f - ALPHA) * (drs * a7) + ALPHA * xb.w;
            }
        }
    }
    __syncthreads();

    // -------- phase 2: 64x64 @ 64x64 GEMM from shared, packed f32x2 FMA ----
    int rl = tid & 63;
    int gq = tid >> 6;          // 4 groups of 16 columns
    int cbase = gq * 16;
    unsigned long long acc[8];
#pragma unroll
    for (int i = 0; i < 8; i++) acc[i] = 0ull;
#pragma unroll 8
    for (int k = 0; k < HID; k++) {
        float sk = ss[rl * 65 + k];
        unsigned long long skk;
        asm("mov.b64 %0, {%1, %2};" : "=l"(skk) : "f"(sk), "f"(sk));
        const ulonglong2* wp = (const ulonglong2*)(Ws + k * HID + cbase);  // warp-uniform
        ulonglong2 p0 = wp[0], p1 = wp[1], p2 = wp[2], p3 = wp[3];
        fma2(acc[0], p0.x, skk); fma2(acc[1], p0.y, skk);
        fma2(acc[2], p1.x, skk); fma2(acc[3], p1.y, skk);
        fma2(acc[4], p2.x, skk); fma2(acc[5], p2.y, skk);
        fma2(acc[6], p3.x, skk); fma2(acc[7], p3.y, skk);
    }
    int r = base + rl;
    if (r < NN) {
        float ob = 1.f - beta;
        float sc = SF * g_dinv[r];
        unsigned short u16[8];
#pragma unroll
        for (int q = 0; q < 8; q++) {
            float lo, hi;
            asm("mov.b64 {%0, %1}, %2;" : "=f"(lo), "=f"(hi) : "l"(acc[q]));
            float v0 = fmaxf(ob * ss[rl * 65 + cbase + 2 * q + 0] + beta * lo, 0.f);
            float v1 = fmaxf(ob * ss[rl * 65 + cbase + 2 * q + 1] + beta * hi, 0.f);
            u16[q] = enc2(sc * v1, sc * v0);
        }
        unsigned int p0 = ((unsigned int)u16[1] << 16) | u16[0];
        unsigned int p1 = ((unsigned int)u16[3] << 16) | u16[2];
        unsigned int p2 = ((unsigned int)u16[5] << 16) | u16[4];
        unsigned int p3 = ((unsigned int)u16[7] << 16) | u16[6];
        *(uint4*)(hout + (size_t)r * HID + cbase) = make_uint4(p0, p1, p2, p3);
    }
}

// ---------------- logits + log_softmax ----------------
__global__ void __launch_bounds__(256) out_kernel(int sel_in,
                                                  const float* __restrict__ W2,
                                                  const float* __restrict__ b2,
                                                  float* __restrict__ out) {
    __shared__ float W2s[HID * NCLASS];
    __shared__ float b2s[NCLASS];
    __shared__ float hrow[8][HID];
    const unsigned char* __restrict__ hin = pick8(sel_in);

    int tid = threadIdx.x;
    for (int i = tid; i < HID * NCLASS; i += 256) W2s[i] = W2[i];
    if (tid < NCLASS) b2s[tid] = b2[tid];
    __syncthreads();

    int w = tid >> 5, lane = tid & 31;
    int r = blockIdx.x * 8 + w;
    if (r < NN && lane < 16) {
        float s = g_rdinv[r] * SFI;   // undo SF*dinv pre-scaling
        unsigned int u = ((const unsigned int*)(hin + (size_t)r * HID))[lane];
        float2 f0, f1;
        dec4(u, f0, f1);
        hrow[w][4 * lane + 0] = s * f0.x;
        hrow[w][4 * lane + 1] = s * f0.y;
        hrow[w][4 * lane + 2] = s * f1.x;
        hrow[w][4 * lane + 3] = s * f1.y;
    }
    __syncwarp();
    if (r >= NN) return;

    int j0 = lane, j1 = lane + 32;
    bool has1 = (j1 < NCLASS);
    float a0 = b2s[j0];
    float a1 = has1 ? b2s[j1] : 0.f;
#pragma unroll 4
    for (int k = 0; k < HID; k++) {
        float hv = hrow[w][k];
        a0 += hv * W2s[k * NCLASS + j0];
        if (has1) a1 += hv * W2s[k * NCLASS + j1];
    }
    float m = a0;
    if (has1) m = fmaxf(m, a1);
#pragma unroll
    for (int off = 16; off; off >>= 1) m = fmaxf(m, __shfl_xor_sync(0xffffffffu, m, off));
    float s = expf(a0 - m) + (has1 ? expf(a1 - m) : 0.f);
#pragma unroll
    for (int off = 16; off; off >>= 1) s += __shfl_xor_sync(0xffffffffu, s, off);
    float lse = m + logf(s);
    out[(size_t)r * NCLASS + j0] = a0 - lse;
    if (has1) out[(size_t)r * NCLASS + j1] = a1 - lse;
}

// ---------------- launch ----------------
extern "C" void kernel_launch(void* const* d_in, const int* in_sizes, int n_in,
                              void* d_out, int out_size) {
    const float* x = (const float*)d_in[0];
    const void* ei = (const void*)d_in[1];
    const float* W1 = (const float*)d_in[2];
    const float* b1 = (const float*)d_in[3];
    const float* convW = (const float*)d_in[4];
    const float* W2 = (const float*)d_in[5];
    const float* b2 = (const float*)d_in[6];
    float* out = (float*)d_out;

    const int TB = 256;
    const int nblkN = (NN + TB - 1) / TB;      // 391
    const int nblkE = (EE + TB - 1) / TB;
    const int nscan = (NN + 1023) / 1024;      // 98
    const int nrowblk = (NN + 63) / 64;        // 1563

    x0_kernel<<<nrowblk, TB>>>(x, W1, b1, (const unsigned int*)ei);
    count_kernel<<<nblkE, TB>>>(ei);
    scan1_kernel<<<nscan, TB>>>();
    scan3_kernel<<<nblkN, TB>>>();
    scatter_kernel<<<nblkE, TB>>>(ei);

    int sel_in = 1;
    for (int l = 0; l < NLAYER; l++) {
        float beta = logf(THETA / (float)(l + 1) + 1.0f);
        int sel_out = 3 - sel_in;
        layer_kernel<<<nrowblk, TB>>>(convW + (size_t)l * HID * HID, beta, sel_in, sel_out);
        sel_in = sel_out;
    }

    out_kernel<<<(NN + 7) / 8, TB>>>(sel_in, W2, b2, out);
}

// round 14
// speedup vs baseline: 1.0817x; 1.0817x over previous
#include <cuda_runtime.h>
#include <cuda_fp16.h>
#include <math.h>

// ---------------- problem constants (fixed-shape problem) ----------------
#define NN 100000
#define EE 3200000
#define F_IN 128
#define HID 64
#define NLAYER 64
#define NCLASS 47
#define ALPHA 0.1f
#define THETA 0.5f
#define SF 32.0f          // fp8 storage scale (keeps values in e4m3 normal range)
#define SFI (1.0f / 32.0f)

// ---------------- scratch (static device globals; no allocation) ---------
// Feature buffers hold PRE-SCALED rows: q = SF * dinv[r] * h[r], e4m3 fp8.
// Row NN is a phantom all-zero row used to pad edge-chunk tails.
__device__ __align__(16) float         g_x0[NN * HID];           // fp32 residual
__device__ __align__(16) unsigned char g_h8A[(NN + 1) * HID];    // ping (fp8)
__device__ __align__(16) unsigned char g_h8B[(NN + 1) * HID];    // pong (fp8)
__device__ int   g_col[EE];          // CSR column indices
__device__ int   g_rowptr[NN + 1];
__device__ int   g_cnt[NN];          // zero at load; self-cleaned each run
__device__ int   g_cursor[NN];
__device__ float g_dinv[NN];         // 1/sqrt(deg+1)
__device__ float g_rdinv[NN];        // sqrt(deg+1)
__device__ int   g_bsum[128];
__device__ int   g_is64;

__device__ __forceinline__ const unsigned char* pick8(int s) {
    return (s == 1) ? g_h8A : g_h8B;
}
__device__ __forceinline__ unsigned char* pick8_mut(int s) {
    return (s == 1) ? g_h8A : g_h8B;
}

// packed f32x2 fma: d = a*b + d
__device__ __forceinline__ void fma2(unsigned long long& d,
                                     unsigned long long a,
                                     unsigned long long b) {
    asm("fma.rn.f32x2 %0, %1, %2, %0;" : "+l"(d) : "l"(a), "l"(b));
}

// decode 4 packed e4m3 -> two half2 (features in byte order)
__device__ __forceinline__ void dec4h(unsigned int u, __half2& h0, __half2& h1) {
    unsigned int a, b;
    asm("{\n\t"
        ".reg .b16 lo, hi;\n\t"
        "mov.b32 {lo, hi}, %2;\n\t"
        "cvt.rn.f16x2.e4m3x2 %0, lo;\n\t"
        "cvt.rn.f16x2.e4m3x2 %1, hi;\n\t"
        "}" : "=r"(a), "=r"(b) : "r"(u));
    h0 = *(__half2*)&a;
    h1 = *(__half2*)&b;
}

// decode 4 packed e4m3 -> two float2
__device__ __forceinline__ void dec4(unsigned int u, float2& f0, float2& f1) {
    __half2 h0, h1;
    dec4h(u, h0, h1);
    f0 = __half22float2(h0);
    f1 = __half22float2(h1);
}

// encode two floats -> 2 packed e4m3 (hi -> upper byte)
__device__ __forceinline__ unsigned short enc2(float hi, float lo) {
    unsigned short p;
    asm("cvt.rn.satfinite.e4m3x2.f32 %0, %1, %2;" : "=h"(p) : "f"(hi), "f"(lo));
    return p;
}

// consume 4 edge-slices (uint = 4 fp8 features each, all same parity group):
// depth-1 fp16 pair tree (e4m3 exact in fp16; one rounding per pair-sum),
// then fp32 accumulate. Short dependence chain on each accumulator.
__device__ __forceinline__ void consume4(const unsigned int ha[4],
                                         float& a0, float& a1,
                                         float& a2, float& a3) {
    __half2 p00, p01, p10, p11, p20, p21, p30, p31;
    dec4h(ha[0], p00, p01);
    dec4h(ha[1], p10, p11);
    dec4h(ha[2], p20, p21);
    dec4h(ha[3], p30, p31);
    __half2 s0 = __hadd2(p00, p10);
    __half2 s1 = __hadd2(p01, p11);
    __half2 t0 = __hadd2(p20, p30);
    __half2 t1 = __hadd2(p21, p31);
    float2 f0 = __half22float2(s0);
    float2 f1 = __half22float2(s1);
    float2 g0 = __half22float2(t0);
    float2 g1 = __half22float2(t1);
    a0 += (f0.x + g0.x);
    a1 += (f0.y + g0.y);
    a2 += (f1.x + g1.x);
    a3 += (f1.y + g1.y);
}

__device__ __forceinline__ int edge_at(const void* eiv, size_t idx, int is64) {
    if (is64) return (int)((const long long*)eiv)[idx];
    return ((const int*)eiv)[idx];
}

// ---------------- x0 = relu(x @ W1 + b1)  (+ inline edge-dtype detect) ----
__global__ void __launch_bounds__(256) x0_kernel(const float* __restrict__ x,
                                                 const float* __restrict__ W1,
                                                 const float* __restrict__ b1,
                                                 const unsigned int* __restrict__ eip) {
    if (blockIdx.x == 0 && threadIdx.x == 0) {
        int all0 = 1;
        for (int i = 0; i < 64; i++) {
            if (eip[2 * i + 1] != 0u) { all0 = 0; break; }
        }
        g_is64 = all0;
    }

    __shared__ __align__(16) float Ws[F_IN * HID];  // 32KB
    int tid = threadIdx.x;
    const float4* W4 = (const float4*)W1;
    float4* Ws4 = (float4*)Ws;
#pragma unroll
    for (int i = tid; i < (F_IN * HID) / 4; i += 256) Ws4[i] = W4[i];
    __syncthreads();

    int base = blockIdx.x * 64;
    int w = tid >> 5, lane = tid & 31;
    float bx = b1[2 * lane], by = b1[2 * lane + 1];
#pragma unroll 1
    for (int i = 0; i < 8; i++) {
        int r = base + w * 8 + i;
        if (r >= NN) continue;
        float ax = bx, ay = by;
        const float4* xr = (const float4*)(x + (size_t)r * F_IN);
#pragma unroll 8
        for (int kk = 0; kk < F_IN / 4; kk++) {
            float4 xv = xr[kk];
            int k = kk * 4;
            float2 w0 = ((const float2*)(Ws + (k + 0) * HID))[lane];
            float2 w1 = ((const float2*)(Ws + (k + 1) * HID))[lane];
            float2 w2 = ((const float2*)(Ws + (k + 2) * HID))[lane];
            float2 w3 = ((const float2*)(Ws + (k + 3) * HID))[lane];
            ax += xv.x * w0.x; ay += xv.x * w0.y;
            ax += xv.y * w1.x; ay += xv.y * w1.y;
            ax += xv.z * w2.x; ay += xv.z * w2.y;
            ax += xv.w * w3.x; ay += xv.w * w3.y;
        }
        float vx = fmaxf(ax, 0.f), vy = fmaxf(ay, 0.f);
        ((float2*)(g_x0 + (size_t)r * HID))[lane] = make_float2(vx, vy);
    }
}

// ---------------- CSR: count ----------------
__global__ void count_kernel(const void* __restrict__ eiv) {
    int i = blockIdx.x * blockDim.x + threadIdx.x;
    int is64 = g_is64;
    if (i < EE) {
        int dst = edge_at(eiv, (size_t)EE + i, is64);
        atomicAdd(&g_cnt[dst], 1);
    }
}

// ---------------- CSR: block-local exclusive scan (1024 per block) -------
__global__ void scan1_kernel() {
    __shared__ int sh[256];
    int t = threadIdx.x, b = blockIdx.x;
    int base = b * 1024 + t * 4;
    int v0 = (base + 0 < NN) ? g_cnt[base + 0] : 0;
    int v1 = (base + 1 < NN) ? g_cnt[base + 1] : 0;
    int v2 = (base + 2 < NN) ? g_cnt[base + 2] : 0;
    int v3 = (base + 3 < NN) ? g_cnt[base + 3] : 0;
    int s0 = v0, s1 = s0 + v1, s2 = s1 + v2, s3 = s2 + v3;
    sh[t] = s3;
    __syncthreads();
    for (int off = 1; off < 256; off <<= 1) {
        int v = (t >= off) ? sh[t - off] : 0;
        __syncthreads();
        sh[t] += v;
        __syncthreads();
    }
    int excl = sh[t] - s3;
    if (base + 0 < NN) g_rowptr[base + 0] = excl;
    if (base + 1 < NN) g_rowptr[base + 1] = excl + s0;
    if (base + 2 < NN) g_rowptr[base + 2] = excl + s1;
    if (base + 3 < NN) g_rowptr[base + 3] = excl + s2;
    if (t == 255) g_bsum[b] = sh[255];
}

// ---------------- CSR: finalize (inline bsum prefix) + dinv + seed h8A ---
__global__ void __launch_bounds__(256) scan3_kernel() {
    __shared__ int pre_sh;
    int t = threadIdx.x, b = blockIdx.x;
    if (t == 0) {
        int nb = b >> 2;
        int run = 0;
        for (int j = 0; j < nb; j++) run += g_bsum[j];
        pre_sh = run;
    }
    __syncthreads();
    int i = b * 256 + t;
    if (i < NN) {
        int rp = g_rowptr[i] + pre_sh;
        g_rowptr[i] = rp;
        g_cursor[i] = rp;
        int deg = g_cnt[i] + 1;
        float di = rsqrtf((float)deg);
        g_dinv[i] = di;
        g_rdinv[i] = sqrtf((float)deg);
        g_cnt[i] = 0;
        // seed h8A with q0 = SF * dinv * x0 (fp8 e4m3)
        float s = SF * di;
        const float4* xr = (const float4*)(g_x0 + (size_t)i * HID);
        unsigned int* hw = (unsigned int*)(g_h8A + (size_t)i * HID);
#pragma unroll
        for (int k = 0; k < 16; k++) {
            float4 v = xr[k];
            unsigned short lo = enc2(s * v.y, s * v.x);
            unsigned short hi = enc2(s * v.w, s * v.z);
            hw[k] = ((unsigned int)hi << 16) | lo;
        }
    }
    if (i == 0) g_rowptr[NN] = EE;
    if (b == 0 && t < 16) {       // phantom row NN = 0 in both buffers
        ((unsigned int*)(g_h8A + (size_t)NN * HID))[t] = 0u;
        ((unsigned int*)(g_h8B + (size_t)NN * HID))[t] = 0u;
    }
}

// ---------------- CSR: scatter ----------------
__global__ void scatter_kernel(const void* __restrict__ eiv) {
    int i = blockIdx.x * blockDim.x + threadIdx.x;
    int is64 = g_is64;
    if (i < EE) {
        int src = edge_at(eiv, (size_t)i, is64);
        int dst = edge_at(eiv, (size_t)EE + i, is64);
        int pos = atomicAdd(&g_cursor[dst], 1);
        g_col[pos] = src;
    }
}

// ---------------- fused layer --------------------------------------------
// phase 1: p[r] = (dinv[r]/SF) * (sum_edges q[c] + q[r])   (pure sum, fp8 rows)
//          s    = (1-a)*p + a*x0
// phase 2: h = relu((1-b)s + b*(s@W));  store q = SF*dinv[r]*h as fp8
__global__ void __launch_bounds__(256) layer_kernel(const float* __restrict__ Wl,
                                                    float beta, int sel_in, int sel_out) {
    __shared__ __align__(16) float Ws[HID * HID];    // 16KB
    __shared__ __align__(16) float ss[64 * 65];      // 16.6KB, pitch 65
    const unsigned char* __restrict__ hin = pick8(sel_in);
    unsigned char* __restrict__ hout = pick8_mut(sel_out);

    int tid = threadIdx.x;
    {   // stage Wl
        const float4* W4 = (const float4*)Wl;
        float4* Ws4 = (float4*)Ws;
#pragma unroll
        for (int i = tid; i < (HID * HID) / 4; i += 256) Ws4[i] = W4[i];
    }

    int base = blockIdx.x * 64;
    int w = tid >> 5, lane = tid & 31;
    int g = lane >> 4;          // edge parity group (0/1)
    int t = lane & 15;          // feature slot: features 4t..4t+3 (4 fp8 = uint)
    const unsigned FULL = 0xffffffffu;

    // -------- phase 1: warp-per-row unweighted gather (R12 structure) -----
    // 32 cols coalesced per chunk; 8-edge subchunks (4 slices/parity, 2
    // edges per LDG.32 warp-instr), double-buffered. Tail lanes already
    // hold phantom col NN, so shfl(cw, idx>=rem) yields NN with NO
    // predicate in the hot loop. fp16 pair-tree then fp32 accumulate.
#pragma unroll 1
    for (int i = 0; i < 8; i++) {
        int rl = w * 8 + i;
        int r = base + rl;
        if (r < NN) {
            float a0 = 0.f, a1 = 0.f, a2 = 0.f, a3 = 0.f;
            int e = g_rowptr[r];
            const int e1 = g_rowptr[r + 1];
#pragma unroll 1
            while (e < e1) {
                int rem = e1 - e;
                int cw = (lane < rem) ? g_col[e + lane] : NN;  // pad -> phantom
                int np = rem < 32 ? rem : 32;
                int nsub = (np + 7) >> 3;

                unsigned int ha[4];
#pragma unroll
                for (int q = 0; q < 4; q++) {
                    int c = __shfl_sync(FULL, cw, 2 * q + g);
                    ha[q] = ((const unsigned int*)(hin + (size_t)c * HID))[t];
                }
#pragma unroll 1
                for (int s = 1; s < nsub; s++) {
                    unsigned int hb[4];
#pragma unroll
                    for (int q = 0; q < 4; q++) {
                        int c = __shfl_sync(FULL, cw, 8 * s + 2 * q + g);
                        hb[q] = ((const unsigned int*)(hin + (size_t)c * HID))[t];
                    }
                    consume4(ha, a0, a1, a2, a3);
#pragma unroll
                    for (int q = 0; q < 4; q++) ha[q] = hb[q];
                }
                consume4(ha, a0, a1, a2, a3);
                e += 32;
            }
            // combine the two 16-lane halves
            a0 += __shfl_xor_sync(FULL, a0, 16);
            a1 += __shfl_xor_sync(FULL, a1, 16);
            a2 += __shfl_xor_sync(FULL, a2, 16);
            a3 += __shfl_xor_sync(FULL, a3, 16);
            // self loop: + q[r]
            {
                unsigned int hs = ((const unsigned int*)(hin + (size_t)r * HID))[t];
                float2 f0, f1;
                dec4(hs, f0, f1);
                a0 += f0.x; a1 += f0.y; a2 += f1.x; a3 += f1.y;
            }
            float drs = g_dinv[r] * SFI;
            float4 x0v = ((const float4*)(g_x0 + (size_t)r * HID))[t];
            if (lane < 16) {
                int bsh = rl * 65 + 4 * t;
                ss[bsh + 0] = (1.f - ALPHA) * (drs * a0) + ALPHA * x0v.x;
                ss[bsh + 1] = (1.f - ALPHA) * (drs * a1) + ALPHA * x0v.y;
                ss[bsh + 2] = (1.f - ALPHA) * (drs * a2) + ALPHA * x0v.z;
                ss[bsh + 3] = (1.f - ALPHA) * (drs * a3) + ALPHA * x0v.w;
            }
        }
    }
    __syncthreads();

    // -------- phase 2: 64x64 @ 64x64 GEMM from shared, packed f32x2 FMA ----
    int rl = tid & 63;
    int gq = tid >> 6;          // 4 groups of 16 columns
    int cbase = gq * 16;
    unsigned long long acc[8];
#pragma unroll
    for (int i = 0; i < 8; i++) acc[i] = 0ull;
#pragma unroll 8
    for (int k = 0; k < HID; k++) {
        float sk = ss[rl * 65 + k];
        unsigned long long skk;
        asm("mov.b64 %0, {%1, %2};" : "=l"(skk) : "f"(sk), "f"(sk));
        const ulonglong2* wp = (const ulonglong2*)(Ws + k * HID + cbase);  // warp-uniform
        ulonglong2 p0 = wp[0], p1 = wp[1], p2 = wp[2], p3 = wp[3];
        fma2(acc[0], p0.x, skk); fma2(acc[1], p0.y, skk);
        fma2(acc[2], p1.x, skk); fma2(acc[3], p1.y, skk);
        fma2(acc[4], p2.x, skk); fma2(acc[5], p2.y, skk);
        fma2(acc[6], p3.x, skk); fma2(acc[7], p3.y, skk);
    }
    int r = base + rl;
    if (r < NN) {
        float ob = 1.f - beta;
        float sc = SF * g_dinv[r];
        unsigned short u16[8];
#pragma unroll
        for (int q = 0; q < 8; q++) {
            float lo, hi;
            asm("mov.b64 {%0, %1}, %2;" : "=f"(lo), "=f"(hi) : "l"(acc[q]));
            float v0 = fmaxf(ob * ss[rl * 65 + cbase + 2 * q + 0] + beta * lo, 0.f);
            float v1 = fmaxf(ob * ss[rl * 65 + cbase + 2 * q + 1] + beta * hi, 0.f);
            u16[q] = enc2(sc * v1, sc * v0);
        }
        unsigned int p0 = ((unsigned int)u16[1] << 16) | u16[0];
        unsigned int p1 = ((unsigned int)u16[3] << 16) | u16[2];
        unsigned int p2 = ((unsigned int)u16[5] << 16) | u16[4];
        unsigned int p3 = ((unsigned int)u16[7] << 16) | u16[6];
        *(uint4*)(hout + (size_t)r * HID + cbase) = make_uint4(p0, p1, p2, p3);
    }
}

// ---------------- logits + log_softmax ----------------
__global__ void __launch_bounds__(256) out_kernel(int sel_in,
                                                  const float* __restrict__ W2,
                                                  const float* __restrict__ b2,
                                                  float* __restrict__ out) {
    __shared__ float W2s[HID * NCLASS];
    __shared__ float b2s[NCLASS];
    __shared__ float hrow[8][HID];
    const unsigned char* __restrict__ hin = pick8(sel_in);

    int tid = threadIdx.x;
    for (int i = tid; i < HID * NCLASS; i += 256) W2s[i] = W2[i];
    if (tid < NCLASS) b2s[tid] = b2[tid];
    __syncthreads();

    int w = tid >> 5, lane = tid & 31;
    int r = blockIdx.x * 8 + w;
    if (r < NN && lane < 16) {
        float s = g_rdinv[r] * SFI;   // undo SF*dinv pre-scaling
        unsigned int u = ((const unsigned int*)(hin + (size_t)r * HID))[lane];
        float2 f0, f1;
        dec4(u, f0, f1);
        hrow[w][4 * lane + 0] = s * f0.x;
        hrow[w][4 * lane + 1] = s * f0.y;
        hrow[w][4 * lane + 2] = s * f1.x;
        hrow[w][4 * lane + 3] = s * f1.y;
    }
    __syncwarp();
    if (r >= NN) return;

    int j0 = lane, j1 = lane + 32;
    bool has1 = (j1 < NCLASS);
    float a0 = b2s[j0];
    float a1 = has1 ? b2s[j1] : 0.f;
#pragma unroll 4
    for (int k = 0; k < HID; k++) {
        float hv = hrow[w][k];
        a0 += hv * W2s[k * NCLASS + j0];
        if (has1) a1 += hv * W2s[k * NCLASS + j1];
    }
    float m = a0;
    if (has1) m = fmaxf(m, a1);
#pragma unroll
    for (int off = 16; off; off >>= 1) m = fmaxf(m, __shfl_xor_sync(0xffffffffu, m, off));
    float s = expf(a0 - m) + (has1 ? expf(a1 - m) : 0.f);
#pragma unroll
    for (int off = 16; off; off >>= 1) s += __shfl_xor_sync(0xffffffffu, s, off);
    float lse = m + logf(s);
    out[(size_t)r * NCLASS + j0] = a0 - lse;
    if (has1) out[(size_t)r * NCLASS + j1] = a1 - lse;
}

// ---------------- launch ----------------
extern "C" void kernel_launch(void* const* d_in, const int* in_sizes, int n_in,
                              void* d_out, int out_size) {
    const float* x = (const float*)d_in[0];
    const void* ei = (const void*)d_in[1];
    const float* W1 = (const float*)d_in[2];
    const float* b1 = (const float*)d_in[3];
    const float* convW = (const float*)d_in[4];
    const float* W2 = (const float*)d_in[5];
    const float* b2 = (const float*)d_in[6];
    float* out = (float*)d_out;

    const int TB = 256;
    const int nblkN = (NN + TB - 1) / TB;      // 391
    const int nblkE = (EE + TB - 1) / TB;
    const int nscan = (NN + 1023) / 1024;      // 98
    const int nrowblk = (NN + 63) / 64;        // 1563

    x0_kernel<<<nrowblk, TB>>>(x, W1, b1, (const unsigned int*)ei);
    count_kernel<<<nblkE, TB>>>(ei);
    scan1_kernel<<<nscan, TB>>>();
    scan3_kernel<<<nblkN, TB>>>();
    scatter_kernel<<<nblkE, TB>>>(ei);

    int sel_in = 1;
    for (int l = 0; l < NLAYER; l++) {
        float beta = logf(THETA / (float)(l + 1) + 1.0f);
        int sel_out = 3 - sel_in;
        layer_kernel<<<nrowblk, TB>>>(convW + (size_t)l * HID * HID, beta, sel_in, sel_out);
        sel_in = sel_out;
    }

    out_kernel<<<(NN + 7) / 8, TB>>>(sel_in, W2, b2, out);
}

// round 15
// speedup vs baseline: 1.1268x; 1.0417x over previous
#include <cuda_runtime.h>
#include <cuda_fp16.h>
#include <math.h>

// ---------------- problem constants (fixed-shape problem) ----------------
#define NN 100000
#define EE 3200000
#define F_IN 128
#define HID 64
#define NLAYER 64
#define NCLASS 47
#define ALPHA 0.1f
#define THETA 0.5f
#define SF 32.0f          // fp8 storage scale (keeps values in e4m3 normal range)
#define SFI (1.0f / 32.0f)

// ---------------- scratch (static device globals; no allocation) ---------
// Feature buffers hold PRE-SCALED rows: q = SF * dinv[r] * h[r], e4m3 fp8.
// Row NN is a phantom all-zero row used to pad edge-chunk tails.
__device__ __align__(16) float         g_x0[NN * HID];           // fp32 residual
__device__ __align__(16) unsigned char g_h8A[(NN + 1) * HID];    // ping (fp8)
__device__ __align__(16) unsigned char g_h8B[(NN + 1) * HID];    // pong (fp8)
__device__ int   g_col[EE];          // CSR column indices
__device__ int   g_rowptr[NN + 1];
__device__ int   g_cnt[NN];          // zero at load; self-cleaned each run
__device__ int   g_cursor[NN];
__device__ float g_dinv[NN];         // 1/sqrt(deg+1)
__device__ float g_rdinv[NN];        // sqrt(deg+1)
__device__ int   g_bsum[128];
__device__ int   g_is64;

__device__ __forceinline__ const unsigned char* pick8(int s) {
    return (s == 1) ? g_h8A : g_h8B;
}
__device__ __forceinline__ unsigned char* pick8_mut(int s) {
    return (s == 1) ? g_h8A : g_h8B;
}

// packed f32x2 fma: d = a*b + d
__device__ __forceinline__ void fma2(unsigned long long& d,
                                     unsigned long long a,
                                     unsigned long long b) {
    asm("fma.rn.f32x2 %0, %1, %2, %0;" : "+l"(d) : "l"(a), "l"(b));
}

// decode 4 packed e4m3 -> two half2 (features in byte order)
__device__ __forceinline__ void dec4h(unsigned int u, __half2& h0, __half2& h1) {
    unsigned int a, b;
    asm("{\n\t"
        ".reg .b16 lo, hi;\n\t"
        "mov.b32 {lo, hi}, %2;\n\t"
        "cvt.rn.f16x2.e4m3x2 %0, lo;\n\t"
        "cvt.rn.f16x2.e4m3x2 %1, hi;\n\t"
        "}" : "=r"(a), "=r"(b) : "r"(u));
    h0 = *(__half2*)&a;
    h1 = *(__half2*)&b;
}

// decode 4 packed e4m3 -> two float2
__device__ __forceinline__ void dec4(unsigned int u, float2& f0, float2& f1) {
    __half2 h0, h1;
    dec4h(u, h0, h1);
    f0 = __half22float2(h0);
    f1 = __half22float2(h1);
}

// encode two floats -> 2 packed e4m3 (hi -> upper byte)
__device__ __forceinline__ unsigned short enc2(float hi, float lo) {
    unsigned short p;
    asm("cvt.rn.satfinite.e4m3x2.f32 %0, %1, %2;" : "=h"(p) : "f"(hi), "f"(lo));
    return p;
}

// consume 4 edge-slices (uint = 4 fp8 features each, all same parity group):
// depth-1 fp16 pair tree (e4m3 exact in fp16; one rounding per pair-sum),
// then fp32 accumulate.
__device__ __forceinline__ void consume4(const unsigned int ha[4],
                                         float& a0, float& a1,
                                         float& a2, float& a3) {
    __half2 p00, p01, p10, p11, p20, p21, p30, p31;
    dec4h(ha[0], p00, p01);
    dec4h(ha[1], p10, p11);
    dec4h(ha[2], p20, p21);
    dec4h(ha[3], p30, p31);
    __half2 s0 = __hadd2(p00, p10);
    __half2 s1 = __hadd2(p01, p11);
    __half2 t0 = __hadd2(p20, p30);
    __half2 t1 = __hadd2(p21, p31);
    float2 f0 = __half22float2(s0);
    float2 f1 = __half22float2(s1);
    float2 g0 = __half22float2(t0);
    float2 g1 = __half22float2(t1);
    a0 += (f0.x + g0.x);
    a1 += (f0.y + g0.y);
    a2 += (f1.x + g1.x);
    a3 += (f1.y + g1.y);
}

__device__ __forceinline__ int edge_at(const void* eiv, size_t idx, int is64) {
    if (is64) return (int)((const long long*)eiv)[idx];
    return ((const int*)eiv)[idx];
}

// ---------------- x0 = relu(x @ W1 + b1)  (+ inline edge-dtype detect) ----
__global__ void __launch_bounds__(256) x0_kernel(const float* __restrict__ x,
                                                 const float* __restrict__ W1,
                                                 const float* __restrict__ b1,
                                                 const unsigned int* __restrict__ eip) {
    if (blockIdx.x == 0 && threadIdx.x == 0) {
        int all0 = 1;
        for (int i = 0; i < 64; i++) {
            if (eip[2 * i + 1] != 0u) { all0 = 0; break; }
        }
        g_is64 = all0;
    }

    __shared__ __align__(16) float Ws[F_IN * HID];  // 32KB
    int tid = threadIdx.x;
    const float4* W4 = (const float4*)W1;
    float4* Ws4 = (float4*)Ws;
#pragma unroll
    for (int i = tid; i < (F_IN * HID) / 4; i += 256) Ws4[i] = W4[i];
    __syncthreads();

    int base = blockIdx.x * 64;
    int w = tid >> 5, lane = tid & 31;
    float bx = b1[2 * lane], by = b1[2 * lane + 1];
#pragma unroll 1
    for (int i = 0; i < 8; i++) {
        int r = base + w * 8 + i;
        if (r >= NN) continue;
        float ax = bx, ay = by;
        const float4* xr = (const float4*)(x + (size_t)r * F_IN);
#pragma unroll 8
        for (int kk = 0; kk < F_IN / 4; kk++) {
            float4 xv = xr[kk];
            int k = kk * 4;
            float2 w0 = ((const float2*)(Ws + (k + 0) * HID))[lane];
            float2 w1 = ((const float2*)(Ws + (k + 1) * HID))[lane];
            float2 w2 = ((const float2*)(Ws + (k + 2) * HID))[lane];
            float2 w3 = ((const float2*)(Ws + (k + 3) * HID))[lane];
            ax += xv.x * w0.x; ay += xv.x * w0.y;
            ax += xv.y * w1.x; ay += xv.y * w1.y;
            ax += xv.z * w2.x; ay += xv.z * w2.y;
            ax += xv.w * w3.x; ay += xv.w * w3.y;
        }
        float vx = fmaxf(ax, 0.f), vy = fmaxf(ay, 0.f);
        ((float2*)(g_x0 + (size_t)r * HID))[lane] = make_float2(vx, vy);
    }
}

// ---------------- CSR: count ----------------
__global__ void count_kernel(const void* __restrict__ eiv) {
    int i = blockIdx.x * blockDim.x + threadIdx.x;
    int is64 = g_is64;
    if (i < EE) {
        int dst = edge_at(eiv, (size_t)EE + i, is64);
        atomicAdd(&g_cnt[dst], 1);
    }
}

// ---------------- CSR: block-local exclusive scan (1024 per block) -------
__global__ void scan1_kernel() {
    __shared__ int sh[256];
    int t = threadIdx.x, b = blockIdx.x;
    int base = b * 1024 + t * 4;
    int v0 = (base + 0 < NN) ? g_cnt[base + 0] : 0;
    int v1 = (base + 1 < NN) ? g_cnt[base + 1] : 0;
    int v2 = (base + 2 < NN) ? g_cnt[base + 2] : 0;
    int v3 = (base + 3 < NN) ? g_cnt[base + 3] : 0;
    int s0 = v0, s1 = s0 + v1, s2 = s1 + v2, s3 = s2 + v3;
    sh[t] = s3;
    __syncthreads();
    for (int off = 1; off < 256; off <<= 1) {
        int v = (t >= off) ? sh[t - off] : 0;
        __syncthreads();
        sh[t] += v;
        __syncthreads();
    }
    int excl = sh[t] - s3;
    if (base + 0 < NN) g_rowptr[base + 0] = excl;
    if (base + 1 < NN) g_rowptr[base + 1] = excl + s0;
    if (base + 2 < NN) g_rowptr[base + 2] = excl + s1;
    if (base + 3 < NN) g_rowptr[base + 3] = excl + s2;
    if (t == 255) g_bsum[b] = sh[255];
}

// ---------------- CSR: finalize (inline bsum prefix) + dinv + seed h8A ---
__global__ void __launch_bounds__(256) scan3_kernel() {
    __shared__ int pre_sh;
    int t = threadIdx.x, b = blockIdx.x;
    if (t == 0) {
        int nb = b >> 2;
        int run = 0;
        for (int j = 0; j < nb; j++) run += g_bsum[j];
        pre_sh = run;
    }
    __syncthreads();
    int i = b * 256 + t;
    if (i < NN) {
        int rp = g_rowptr[i] + pre_sh;
        g_rowptr[i] = rp;
        g_cursor[i] = rp;
        int deg = g_cnt[i] + 1;
        float di = rsqrtf((float)deg);
        g_dinv[i] = di;
        g_rdinv[i] = sqrtf((float)deg);
        g_cnt[i] = 0;
        // seed h8A with q0 = SF * dinv * x0 (fp8 e4m3)
        float s = SF * di;
        const float4* xr = (const float4*)(g_x0 + (size_t)i * HID);
        unsigned int* hw = (unsigned int*)(g_h8A + (size_t)i * HID);
#pragma unroll
        for (int k = 0; k < 16; k++) {
            float4 v = xr[k];
            unsigned short lo = enc2(s * v.y, s * v.x);
            unsigned short hi = enc2(s * v.w, s * v.z);
            hw[k] = ((unsigned int)hi << 16) | lo;
        }
    }
    if (i == 0) g_rowptr[NN] = EE;
    if (b == 0 && t < 16) {       // phantom row NN = 0 in both buffers
        ((unsigned int*)(g_h8A + (size_t)NN * HID))[t] = 0u;
        ((unsigned int*)(g_h8B + (size_t)NN * HID))[t] = 0u;
    }
}

// ---------------- CSR: scatter ----------------
__global__ void scatter_kernel(const void* __restrict__ eiv) {
    int i = blockIdx.x * blockDim.x + threadIdx.x;
    int is64 = g_is64;
    if (i < EE) {
        int src = edge_at(eiv, (size_t)i, is64);
        int dst = edge_at(eiv, (size_t)EE + i, is64);
        int pos = atomicAdd(&g_cursor[dst], 1);
        g_col[pos] = src;
    }
}

// ---------------- fused layer --------------------------------------------
// phase 1: p[r] = (dinv[r]/SF) * (sum_edges q[c] + q[r])   (pure sum, fp8 rows)
//          s    = (1-a)*p + a*x0            (stored fp16 in shared, pitch 66)
// phase 2: h = relu((1-b)s + b*(s@W));  store q = SF*dinv[r]*h as fp8
__global__ void __launch_bounds__(256, 8) layer_kernel(const float* __restrict__ Wl,
                                                       float beta, int sel_in, int sel_out) {
    __shared__ __align__(16) float  Ws[HID * HID];   // 16KB
    __shared__ __align__(16) __half ssh[64 * 66];    // 8.25KB fp16 s, pitch 66
    const unsigned char* __restrict__ hin = pick8(sel_in);
    unsigned char* __restrict__ hout = pick8_mut(sel_out);

    int tid = threadIdx.x;
    {   // stage Wl
        const float4* W4 = (const float4*)Wl;
        float4* Ws4 = (float4*)Ws;
#pragma unroll
        for (int i = tid; i < (HID * HID) / 4; i += 256) Ws4[i] = W4[i];
    }

    int base = blockIdx.x * 64;
    int w = tid >> 5, lane = tid & 31;
    int g = lane >> 4;          // edge parity group (0/1)
    int t = lane & 15;          // feature slot: features 4t..4t+3 (4 fp8 = uint)
    const unsigned FULL = 0xffffffffu;

    // -------- phase 1: warp-per-row unweighted gather (R14 structure) -----
#pragma unroll 1
    for (int i = 0; i < 8; i++) {
        int rl = w * 8 + i;
        int r = base + rl;
        if (r < NN) {
            float a0 = 0.f, a1 = 0.f, a2 = 0.f, a3 = 0.f;
            int e = g_rowptr[r];
            const int e1 = g_rowptr[r + 1];
#pragma unroll 1
            while (e < e1) {
                int rem = e1 - e;
                int cw = (lane < rem) ? g_col[e + lane] : NN;  // pad -> phantom
                int np = rem < 32 ? rem : 32;
                int nsub = (np + 7) >> 3;

                unsigned int ha[4];
#pragma unroll
                for (int q = 0; q < 4; q++) {
                    int c = __shfl_sync(FULL, cw, 2 * q + g);
                    ha[q] = ((const unsigned int*)(hin + (size_t)c * HID))[t];
                }
#pragma unroll 1
                for (int s = 1; s < nsub; s++) {
                    unsigned int hb[4];
#pragma unroll
                    for (int q = 0; q < 4; q++) {
                        int c = __shfl_sync(FULL, cw, 8 * s + 2 * q + g);
                        hb[q] = ((const unsigned int*)(hin + (size_t)c * HID))[t];
                    }
                    consume4(ha, a0, a1, a2, a3);
#pragma unroll
                    for (int q = 0; q < 4; q++) ha[q] = hb[q];
                }
                consume4(ha, a0, a1, a2, a3);
                e += 32;
            }
            // combine the two 16-lane halves
            a0 += __shfl_xor_sync(FULL, a0, 16);
            a1 += __shfl_xor_sync(FULL, a1, 16);
            a2 += __shfl_xor_sync(FULL, a2, 16);
            a3 += __shfl_xor_sync(FULL, a3, 16);
            // self loop: + q[r]
            {
                unsigned int hs = ((const unsigned int*)(hin + (size_t)r * HID))[t];
                float2 f0, f1;
                dec4(hs, f0, f1);
                a0 += f0.x; a1 += f0.y; a2 += f1.x; a3 += f1.y;
            }
            float drs = g_dinv[r] * SFI;
            float4 x0v = ((const float4*)(g_x0 + (size_t)r * HID))[t];
            if (lane < 16) {
                float s0 = (1.f - ALPHA) * (drs * a0) + ALPHA * x0v.x;
                float s1 = (1.f - ALPHA) * (drs * a1) + ALPHA * x0v.y;
                float s2 = (1.f - ALPHA) * (drs * a2) + ALPHA * x0v.z;
                float s3 = (1.f - ALPHA) * (drs * a3) + ALPHA * x0v.w;
                __half2* sp = (__half2*)ssh + rl * 33 + 2 * t;
                sp[0] = __floats2half2_rn(s0, s1);
                sp[1] = __floats2half2_rn(s2, s3);
            }
        }
    }
    __syncthreads();

    // -------- phase 2: 64x64 @ 64x64 GEMM (s fp16 in shared, W fp32) ------
    int rl = tid & 63;
    int gq = tid >> 6;          // 4 groups of 16 columns
    int cbase = gq * 16;
    const __half2* srow = (const __half2*)ssh + rl * 33;  // bank = (rl+kk)%32
    unsigned long long acc[8];
#pragma unroll
    for (int i = 0; i < 8; i++) acc[i] = 0ull;
#pragma unroll 4
    for (int kk = 0; kk < HID / 2; kk++) {
        float2 skf = __half22float2(srow[kk]);
        unsigned long long sk0, sk1;
        asm("mov.b64 %0, {%1, %1};" : "=l"(sk0) : "f"(skf.x));
        asm("mov.b64 %0, {%1, %1};" : "=l"(sk1) : "f"(skf.y));
        {
            const ulonglong2* wp = (const ulonglong2*)(Ws + (2 * kk) * HID + cbase);
            ulonglong2 p0 = wp[0], p1 = wp[1], p2 = wp[2], p3 = wp[3];
            fma2(acc[0], p0.x, sk0); fma2(acc[1], p0.y, sk0);
            fma2(acc[2], p1.x, sk0); fma2(acc[3], p1.y, sk0);
            fma2(acc[4], p2.x, sk0); fma2(acc[5], p2.y, sk0);
            fma2(acc[6], p3.x, sk0); fma2(acc[7], p3.y, sk0);
        }
        {
            const ulonglong2* wp = (const ulonglong2*)(Ws + (2 * kk + 1) * HID + cbase);
            ulonglong2 p0 = wp[0], p1 = wp[1], p2 = wp[2], p3 = wp[3];
            fma2(acc[0], p0.x, sk1); fma2(acc[1], p0.y, sk1);
            fma2(acc[2], p1.x, sk1); fma2(acc[3], p1.y, sk1);
            fma2(acc[4], p2.x, sk1); fma2(acc[5], p2.y, sk1);
            fma2(acc[6], p3.x, sk1); fma2(acc[7], p3.y, sk1);
        }
    }
    int r = base + rl;
    if (r < NN) {
        float ob = 1.f - beta;
        float sc = SF * g_dinv[r];
        unsigned short u16[8];
#pragma unroll
        for (int q = 0; q < 8; q++) {
            float lo, hi;
            asm("mov.b64 {%0, %1}, %2;" : "=f"(lo), "=f"(hi) : "l"(acc[q]));
            float2 sres = __half22float2(srow[(cbase >> 1) + q]);
            float v0 = fmaxf(ob * sres.x + beta * lo, 0.f);
            float v1 = fmaxf(ob * sres.y + beta * hi, 0.f);
            u16[q] = enc2(sc * v1, sc * v0);
        }
        unsigned int p0 = ((unsigned int)u16[1] << 16) | u16[0];
        unsigned int p1 = ((unsigned int)u16[3] << 16) | u16[2];
        unsigned int p2 = ((unsigned int)u16[5] << 16) | u16[4];
        unsigned int p3 = ((unsigned int)u16[7] << 16) | u16[6];
        *(uint4*)(hout + (size_t)r * HID + cbase) = make_uint4(p0, p1, p2, p3);
    }
}

// ---------------- logits + log_softmax ----------------
__global__ void __launch_bounds__(256) out_kernel(int sel_in,
                                                  const float* __restrict__ W2,
                                                  const float* __restrict__ b2,
                                                  float* __restrict__ out) {
    __shared__ float W2s[HID * NCLASS];
    __shared__ float b2s[NCLASS];
    __shared__ float hrow[8][HID];
    const unsigned char* __restrict__ hin = pick8(sel_in);

    int tid = threadIdx.x;
    for (int i = tid; i < HID * NCLASS; i += 256) W2s[i] = W2[i];
    if (tid < NCLASS) b2s[tid] = b2[tid];
    __syncthreads();

    int w = tid >> 5, lane = tid & 31;
    int r = blockIdx.x * 8 + w;
    if (r < NN && lane < 16) {
        float s = g_rdinv[r] * SFI;   // undo SF*dinv pre-scaling
        unsigned int u = ((const unsigned int*)(hin + (size_t)r * HID))[lane];
        float2 f0, f1;
        dec4(u, f0, f1);
        hrow[w][4 * lane + 0] = s * f0.x;
        hrow[w][4 * lane + 1] = s * f0.y;
        hrow[w][4 * lane + 2] = s * f1.x;
        hrow[w][4 * lane + 3] = s * f1.y;
    }
    __syncwarp();
    if (r >= NN) return;

    int j0 = lane, j1 = lane + 32;
    bool has1 = (j1 < NCLASS);
    float a0 = b2s[j0];
    float a1 = has1 ? b2s[j1] : 0.f;
#pragma unroll 4
    for (int k = 0; k < HID; k++) {
        float hv = hrow[w][k];
        a0 += hv * W2s[k * NCLASS + j0];
        if (has1) a1 += hv * W2s[k * NCLASS + j1];
    }
    float m = a0;
    if (has1) m = fmaxf(m, a1);
#pragma unroll
    for (int off = 16; off; off >>= 1) m = fmaxf(m, __shfl_xor_sync(0xffffffffu, m, off));
    float s = expf(a0 - m) + (has1 ? expf(a1 - m) : 0.f);
#pragma unroll
    for (int off = 16; off; off >>= 1) s += __shfl_xor_sync(0xffffffffu, s, off);
    float lse = m + logf(s);
    out[(size_t)r * NCLASS + j0] = a0 - lse;
    if (has1) out[(size_t)r * NCLASS + j1] = a1 - lse;
}

// ---------------- launch ----------------
extern "C" void kernel_launch(void* const* d_in, const int* in_sizes, int n_in,
                              void* d_out, int out_size) {
    const float* x = (const float*)d_in[0];
    const void* ei = (const void*)d_in[1];
    const float* W1 = (const float*)d_in[2];
    const float* b1 = (const float*)d_in[3];
    const float* convW = (const float*)d_in[4];
    const float* W2 = (const float*)d_in[5];
    const float* b2 = (const float*)d_in[6];
    float* out = (float*)d_out;

    const int TB = 256;
    const int nblkN = (NN + TB - 1) / TB;      // 391
    const int nblkE = (EE + TB - 1) / TB;
    const int nscan = (NN + 1023) / 1024;      // 98
    const int nrowblk = (NN + 63) / 64;        // 1563

    x0_kernel<<<nrowblk, TB>>>(x, W1, b1, (const unsigned int*)ei);
    count_kernel<<<nblkE, TB>>>(ei);
    scan1_kernel<<<nscan, TB>>>();
    scan3_kernel<<<nblkN, TB>>>();
    scatter_kernel<<<nblkE, TB>>>(ei);

    int sel_in = 1;
    for (int l = 0; l < NLAYER; l++) {
        float beta = logf(THETA / (float)(l + 1) + 1.0f);
        int sel_out = 3 - sel_in;
        layer_kernel<<<nrowblk, TB>>>(convW + (size_t)l * HID * HID, beta, sel_in, sel_out);
        sel_in = sel_out;
    }

    out_kernel<<<(NN + 7) / 8, TB>>>(sel_in, W2, b2, out);
}